// round 13
// baseline (speedup 1.0000x reference)
#include <cuda_runtime.h>
#include <cuda_bf16.h>
#include <cuda_fp16.h>
#include <cstdint>

// Problem constants
#define NROWS 131072
#define KMU   256
#define DDIM  128
#define MT    128                 // rows per CTA tile
#define NTILES (NROWS / MT)       // 1024
#define NCTAS  304                // 2 per SM on 152-SM GB300
#define THREADS 512               // 16 warps; warp owns 16 of 256 columns

// padded bf16 smem row: 128 bf16 + 8 pad = 272 bytes (conflict-free ldmatrix)
#define RSTRIDE 272
#define BUFSZ   (MT * RSTRIDE)    // 34816 per x buffer

// dynamic smem byte offsets
// prologue: W tile (256 x 272 = 69632) exactly overlays the two x buffers
#define SBUF  0                       // 2 x 34816 = 69632
#define SADJ  69632                   // 256 floats -> 70656
#define SMP   70656                   // 128 x 17 float2 = 17408 -> 88064
#define SRED  88064                   // 16 floats -> 88128
#define SMEM_TOTAL 88128

#define L2E 1.4426950408889634f
#define LN2 0.69314718055994531f

__device__ float g_partials[NCTAS];
__device__ unsigned int g_count = 0;

__device__ __forceinline__ uint32_t smem_u32(const void* p) {
    uint32_t a;
    asm("{ .reg .u64 t; cvta.to.shared.u64 t, %1; cvt.u32.u64 %0, t; }" : "=r"(a) : "l"(p));
    return a;
}

__device__ __forceinline__ void ldm_x4(uint32_t addr, uint32_t& r0, uint32_t& r1,
                                       uint32_t& r2, uint32_t& r3) {
    asm volatile("ldmatrix.sync.aligned.m8n8.x4.shared.b16 {%0,%1,%2,%3}, [%4];"
                 : "=r"(r0), "=r"(r1), "=r"(r2), "=r"(r3) : "r"(addr));
}

__device__ __forceinline__ void mma16816(float* d, const uint32_t* a, const uint32_t* b) {
    asm volatile(
        "mma.sync.aligned.m16n8k16.row.col.f32.bf16.bf16.f32 "
        "{%0,%1,%2,%3}, {%4,%5,%6,%7}, {%8,%9}, {%0,%1,%2,%3};"
        : "+f"(d[0]), "+f"(d[1]), "+f"(d[2]), "+f"(d[3])
        : "r"(a[0]), "r"(a[1]), "r"(a[2]), "r"(a[3]), "r"(b[0]), "r"(b[1]));
}

__device__ __forceinline__ float ex2f(float x) {
    float y; asm("ex2.approx.ftz.f32 %0, %1;" : "=f"(y) : "f"(x)); return y;
}
__device__ __forceinline__ float lg2f(float x) {
    float y; asm("lg2.approx.ftz.f32 %0, %1;" : "=f"(y) : "f"(x)); return y;
}

__device__ __forceinline__ __half2 shfl_xor_h2(__half2 v, int o) {
    uint32_t u = *(uint32_t*)&v;
    u = __shfl_xor_sync(0xFFFFFFFFu, u, o);
    return *(__half2*)&u;
}

__global__ void __launch_bounds__(THREADS, 2)
gmm_lse_kernel(const float* __restrict__ x, const float* __restrict__ mu,
               const float* __restrict__ prec, float* __restrict__ out) {
    extern __shared__ char smem[];
    const uint32_t sb = smem_u32(smem);
    const int tid = threadIdx.x;
    const int w = tid >> 5;           // 0..15
    const int l = tid & 31;
    const int m = l >> 3, r = l & 7;

    float*  adj_s = (float*)(smem + SADJ);
    float2* mp_s  = (float2*)(smem + SMP);
    float*  red_s = (float*)(smem + SRED);
    __shared__ unsigned int last_flag;

    // per-lane precision slice (cols 4l..4l+3)
    const float4 pc = ((const float4*)prec)[l];

    // ---- prologue: stage W = prec*mu as bf16 at offset 0 (256 x 272), adj[k] ----
    {
        const float4* mr = (const float4*)(mu + (long)(w * 16) * DDIM);
        #pragma unroll 4
        for (int i = 0; i < 16; i++) {
            const int krow = w * 16 + i;
            float4 f = mr[i * 32 + l];
            float wx = pc.x * f.x, wy = pc.y * f.y, wz = pc.z * f.z, ww = pc.w * f.w;
            float s = wx * f.x;
            s = fmaf(wy, f.y, s);
            s = fmaf(wz, f.z, s);
            s = fmaf(ww, f.w, s);
            #pragma unroll
            for (int o = 16; o; o >>= 1) s += __shfl_xor_sync(0xFFFFFFFFu, s, o);
            __nv_bfloat162 lo = __floats2bfloat162_rn(wx, wy);
            __nv_bfloat162 hi = __floats2bfloat162_rn(wz, ww);
            uint2 v;
            v.x = *(uint32_t*)&lo;
            v.y = *(uint32_t*)&hi;
            *(uint2*)(smem + krow * RSTRIDE + l * 8) = v;
            if (l == 0) adj_s[krow] = -0.5f * s * L2E;
        }
    }
    __syncthreads();

    // ---- register-resident B fragments: warp w owns cols [16w, 16w+16) ----
    uint32_t B[8][4];     // 32 regs
    #pragma unroll
    for (int ks = 0; ks < 8; ks++) {
        uint32_t addr = sb
            + (w * 16 + ((m >> 1) << 3) + r) * RSTRIDE
            + ((ks << 4) + ((m & 1) << 3)) * 2;
        ldm_x4(addr, B[ks][0], B[ks][1], B[ks][2], B[ks][3]);
    }
    // adj for this lane's 4 columns as half2
    __half2 av_h[2];
    #pragma unroll
    for (int t = 0; t < 2; t++) {
        const int col = w * 16 + 8 * t + 2 * (l & 3);
        av_h[t] = __floats2half2_rn(adj_s[col], adj_s[col + 1]);
    }
    const __half2 l2e2 = __floats2half2_rn(L2E, L2E);
    __syncthreads();   // W region dead; x double-buffer lives at SBUF

    float acc_thr = 0.f;
    float xsq_acc = 0.f;

    // ---- stage first tile into buf0: warp w loads rows w*8..w*8+7 ----
    {
        const int tile0 = blockIdx.x;
        const float4* xr = (const float4*)(x + (long)(tile0 * MT + w * 8) * DDIM);
        #pragma unroll 8
        for (int i = 0; i < 8; i++) {
            float4 f = xr[i * 32 + l];
            xsq_acc = fmaf(pc.x * f.x, f.x, xsq_acc);
            xsq_acc = fmaf(pc.y * f.y, f.y, xsq_acc);
            xsq_acc = fmaf(pc.z * f.z, f.z, xsq_acc);
            xsq_acc = fmaf(pc.w * f.w, f.w, xsq_acc);
            __nv_bfloat162 lo = __floats2bfloat162_rn(f.x, f.y);
            __nv_bfloat162 hi = __floats2bfloat162_rn(f.z, f.w);
            uint2 v;
            v.x = *(uint32_t*)&lo;
            v.y = *(uint32_t*)&hi;
            *(uint2*)(smem + SBUF + (w * 8 + i) * RSTRIDE + l * 8) = v;
        }
    }
    __syncthreads();

    int par = 0;
    for (int tile = blockIdx.x; tile < NTILES; tile += gridDim.x, par ^= 1) {
        const uint32_t cur = sb + SBUF + par * BUFSZ;

        // ---- stage NEXT tile into the other buffer (direct LDG, fire early) ----
        const int nxt = tile + gridDim.x;
        if (nxt < NTILES) {
            const float4* xr = (const float4*)(x + (long)(nxt * MT + w * 8) * DDIM);
            #pragma unroll 8
            for (int i = 0; i < 8; i++) {
                float4 f = xr[i * 32 + l];
                xsq_acc = fmaf(pc.x * f.x, f.x, xsq_acc);
                xsq_acc = fmaf(pc.y * f.y, f.y, xsq_acc);
                xsq_acc = fmaf(pc.z * f.z, f.z, xsq_acc);
                xsq_acc = fmaf(pc.w * f.w, f.w, xsq_acc);
                __nv_bfloat162 lo = __floats2bfloat162_rn(f.x, f.y);
                __nv_bfloat162 hi = __floats2bfloat162_rn(f.z, f.w);
                uint2 v;
                v.x = *(uint32_t*)&lo;
                v.y = *(uint32_t*)&hi;
                *(uint2*)(smem + SBUF + (par ^ 1) * BUFSZ + (w * 8 + i) * RSTRIDE + l * 8) = v;
            }
        }

        // ---- compute: warp w = all 128 rows x its 16 cols ----
        #pragma unroll 1
        for (int mt = 0; mt < 8; mt++) {
            float acc[2][4] = {};
            uint32_t a0[4], a1[4];
            const uint32_t rowad = cur + (mt * 16 + ((m & 1) << 3) + r) * RSTRIDE
                                 + (((m >> 1) << 3)) * 2;
            ldm_x4(rowad, a0[0], a0[1], a0[2], a0[3]);
            #pragma unroll
            for (int ks = 0; ks < 8; ks++) {
                uint32_t* ac = (ks & 1) ? a1 : a0;
                uint32_t* an = (ks & 1) ? a0 : a1;
                if (ks < 7)
                    ldm_x4(rowad + ((ks + 1) << 5), an[0], an[1], an[2], an[3]);
                mma16816(acc[0], ac, &B[ks][0]);
                mma16816(acc[1], ac, &B[ks][2]);
            }
            // ---- half2 epilogue: per-row (max,sum) over this warp's 16 cols ----
            #pragma unroll
            for (int sub = 0; sub < 2; sub++) {
                __half2 v0 = __hfma2(__floats2half2_rn(acc[0][sub * 2], acc[0][sub * 2 + 1]),
                                     l2e2, av_h[0]);
                __half2 v1 = __hfma2(__floats2half2_rn(acc[1][sub * 2], acc[1][sub * 2 + 1]),
                                     l2e2, av_h[1]);
                __half2 mx = __hmax2(v0, v1);
                mx = __hmax2(mx, __lowhigh2highlow(mx));
                mx = __hmax2(mx, shfl_xor_h2(mx, 1));
                mx = __hmax2(mx, shfl_xor_h2(mx, 2));     // row max over 16 cols
                __half2 e0 = h2exp2(__hsub2(v0, mx));
                __half2 e1 = h2exp2(__hsub2(v1, mx));
                e0 = __hadd2(e0, e1);
                e0 = __hadd2(e0, __lowhigh2highlow(e0));
                e0 = __hadd2(e0, shfl_xor_h2(e0, 1));
                e0 = __hadd2(e0, shfl_xor_h2(e0, 2));     // 16-col sum
                if ((l & 3) == 0) {
                    const int row = mt * 16 + sub * 8 + (l >> 2);
                    mp_s[row * 17 + w] = make_float2(__low2float(mx), __low2float(e0));
                }
            }
        }
        __syncthreads();

        // ---- exact 16-way cross-warp merge; threads 0..127 own one row each ----
        if (tid < MT) {
            float m16 = mp_s[tid * 17].x;
            #pragma unroll
            for (int j = 1; j < 16; j++) m16 = fmaxf(m16, mp_s[tid * 17 + j].x);
            float s16 = 0.f;
            #pragma unroll
            for (int j = 0; j < 16; j++) {
                float2 p = mp_s[tid * 17 + j];
                s16 += p.y * ex2f(p.x - m16);
            }
            acc_thr += LN2 * (m16 + lg2f(s16));
        }
        __syncthreads();
    }

    // fold thread-local xsq (additive pass-through of logsumexp)
    acc_thr -= 0.5f * xsq_acc;

    // ---- deterministic block reduction ----
    float a = acc_thr;
    #pragma unroll
    for (int o = 16; o; o >>= 1) a += __shfl_xor_sync(0xFFFFFFFFu, a, o);
    if (l == 0) red_s[w] = a;
    __syncthreads();
    if (tid == 0) {
        float t = 0.f;
        #pragma unroll
        for (int i = 0; i < 16; i++) t += red_s[i];
        g_partials[blockIdx.x] = t;
        __threadfence();
        unsigned int c = atomicAdd(&g_count, 1u);
        last_flag = (c == (unsigned)(gridDim.x - 1)) ? 1u : 0u;
    }
    __syncthreads();

    // ---- last CTA: deterministic final reduction (fixed lane->index map) ----
    if (last_flag && w == 0) {
        float s = 0.f;
        #pragma unroll
        for (int i = l; i < NCTAS; i += 32) s += __ldcg(&g_partials[i]);
        #pragma unroll
        for (int o = 16; o; o >>= 1) s += __shfl_xor_sync(0xFFFFFFFFu, s, o);
        if (l == 0) {
            out[0] = -s;
            g_count = 0;          // reset for next graph replay
            __threadfence();
        }
    }
}

extern "C" void kernel_launch(void* const* d_in, const int* in_sizes, int n_in,
                              void* d_out, int out_size) {
    const float* x    = (const float*)d_in[0];
    const float* mu   = (const float*)d_in[1];
    const float* prec = (const float*)d_in[2];
    float* out = (float*)d_out;

    cudaFuncSetAttribute(gmm_lse_kernel, cudaFuncAttributeMaxDynamicSharedMemorySize, SMEM_TOTAL);
    gmm_lse_kernel<<<NCTAS, THREADS, SMEM_TOTAL>>>(x, mu, prec, out);
}

// round 14
// speedup vs baseline: 1.6133x; 1.6133x over previous
#include <cuda_runtime.h>
#include <cuda_bf16.h>
#include <cstdint>

// Problem constants
#define NROWS 131072
#define KMU   256
#define DDIM  128
#define MT    128                 // rows per CTA tile
#define NTILES (NROWS / MT)       // 1024
#define NCTAS  304                // 2 per SM on 152-SM GB300
#define THREADS 256               // 8 warps; warp owns 32 of 256 columns

// padded bf16 smem row: 128 bf16 + 8 pad = 272 bytes (conflict-free ldmatrix)
#define RSTRIDE 272
#define BUFSZ   (MT * RSTRIDE)    // 34816 per x buffer

// dynamic smem byte offsets
// prologue: W tile (256 x 272 = 69632) exactly overlays the two x buffers
#define SBUF  0                       // 2 x 34816 = 69632
#define SADJ  69632                   // 256 floats -> 70656
#define SPART 70656                   // 128 rows x 36 floats (pad: bank-conflict-free) -> 89088
#define SRED  89088                   // 8 floats -> 89120
#define SMEM_TOTAL 89120

#define L2E 1.4426950408889634f
#define LN2 0.69314718055994531f
#define CSHIFT 32.0f               // centering shift; >70 binades of fp32 margin both sides

__device__ float g_partials[NCTAS];
__device__ unsigned int g_count = 0;

__device__ __forceinline__ uint32_t smem_u32(const void* p) {
    uint32_t a;
    asm("{ .reg .u64 t; cvta.to.shared.u64 t, %1; cvt.u32.u64 %0, t; }" : "=r"(a) : "l"(p));
    return a;
}

__device__ __forceinline__ void ldm_x4(uint32_t addr, uint32_t& r0, uint32_t& r1,
                                       uint32_t& r2, uint32_t& r3) {
    asm volatile("ldmatrix.sync.aligned.m8n8.x4.shared.b16 {%0,%1,%2,%3}, [%4];"
                 : "=r"(r0), "=r"(r1), "=r"(r2), "=r"(r3) : "r"(addr));
}

__device__ __forceinline__ void mma16816(float* d, const uint32_t* a, const uint32_t* b) {
    asm volatile(
        "mma.sync.aligned.m16n8k16.row.col.f32.bf16.bf16.f32 "
        "{%0,%1,%2,%3}, {%4,%5,%6,%7}, {%8,%9}, {%0,%1,%2,%3};"
        : "+f"(d[0]), "+f"(d[1]), "+f"(d[2]), "+f"(d[3])
        : "r"(a[0]), "r"(a[1]), "r"(a[2]), "r"(a[3]), "r"(b[0]), "r"(b[1]));
}

__device__ __forceinline__ float ex2f(float x) {
    float y; asm("ex2.approx.ftz.f32 %0, %1;" : "=f"(y) : "f"(x)); return y;
}
__device__ __forceinline__ float lg2f(float x) {
    float y; asm("lg2.approx.ftz.f32 %0, %1;" : "=f"(y) : "f"(x)); return y;
}

__global__ void __launch_bounds__(THREADS, 2)
gmm_lse_kernel(const float* __restrict__ x, const float* __restrict__ mu,
               const float* __restrict__ prec, float* __restrict__ out) {
    extern __shared__ char smem[];
    const uint32_t sb = smem_u32(smem);
    const int tid = threadIdx.x;
    const int w = tid >> 5;
    const int l = tid & 31;
    const int m = l >> 3, r = l & 7;

    float* adj_s  = (float*)(smem + SADJ);
    float* red_s  = (float*)(smem + SRED);
    __shared__ unsigned int last_flag;

    // per-lane precision slice (cols 4l..4l+3)
    const float4 pc = ((const float4*)prec)[l];

    // ---- prologue: stage W = prec*mu as bf16 at offset 0 (256 x 272), adj[k] ----
    {
        const float4* mr = (const float4*)(mu + (long)(w * 32) * DDIM);
        #pragma unroll 4
        for (int i = 0; i < 32; i++) {
            const int krow = w * 32 + i;
            float4 f = mr[i * 32 + l];
            float wx = pc.x * f.x, wy = pc.y * f.y, wz = pc.z * f.z, ww = pc.w * f.w;
            float s = wx * f.x;
            s = fmaf(wy, f.y, s);
            s = fmaf(wz, f.z, s);
            s = fmaf(ww, f.w, s);
            #pragma unroll
            for (int o = 16; o; o >>= 1) s += __shfl_xor_sync(0xFFFFFFFFu, s, o);
            __nv_bfloat162 lo = __floats2bfloat162_rn(wx, wy);
            __nv_bfloat162 hi = __floats2bfloat162_rn(wz, ww);
            uint2 v;
            v.x = *(uint32_t*)&lo;
            v.y = *(uint32_t*)&hi;
            *(uint2*)(smem + krow * RSTRIDE + l * 8) = v;
            if (l == 0) adj_s[krow] = -0.5f * s * L2E;
        }
    }
    __syncthreads();

    // ---- register-resident B fragments: warp w owns cols [32w, 32w+32) ----
    uint32_t B[8][2][4];   // 64 regs
    #pragma unroll
    for (int ks = 0; ks < 8; ks++) {
        #pragma unroll
        for (int tp = 0; tp < 2; tp++) {
            uint32_t addr = sb
                + (w * 32 + tp * 16 + ((m >> 1) << 3) + r) * RSTRIDE
                + ((ks << 4) + ((m & 1) << 3)) * 2;
            ldm_x4(addr, B[ks][tp][0], B[ks][tp][1], B[ks][tp][2], B[ks][tp][3]);
        }
    }
    // adj (+CSHIFT) for this lane's 8 columns, fp32
    float av[8];
    #pragma unroll
    for (int t = 0; t < 4; t++) {
        const int col = w * 32 + 8 * t + 2 * (l & 3);
        av[2 * t]     = adj_s[col]     + CSHIFT;
        av[2 * t + 1] = adj_s[col + 1] + CSHIFT;
    }
    __syncthreads();   // W region dead; x double-buffer lives at SBUF

    float acc_thr = 0.f;
    float xsq_acc = 0.f;

    // ---- stage first tile into buf0: warp w loads rows w*16..w*16+15 ----
    {
        const int tile0 = blockIdx.x;
        const float4* xr = (const float4*)(x + (long)(tile0 * MT + w * 16) * DDIM);
        #pragma unroll 8
        for (int i = 0; i < 16; i++) {
            float4 f = xr[i * 32 + l];
            xsq_acc = fmaf(pc.x * f.x, f.x, xsq_acc);
            xsq_acc = fmaf(pc.y * f.y, f.y, xsq_acc);
            xsq_acc = fmaf(pc.z * f.z, f.z, xsq_acc);
            xsq_acc = fmaf(pc.w * f.w, f.w, xsq_acc);
            __nv_bfloat162 lo = __floats2bfloat162_rn(f.x, f.y);
            __nv_bfloat162 hi = __floats2bfloat162_rn(f.z, f.w);
            uint2 v;
            v.x = *(uint32_t*)&lo;
            v.y = *(uint32_t*)&hi;
            *(uint2*)(smem + SBUF + (w * 16 + i) * RSTRIDE + l * 8) = v;
        }
    }
    __syncthreads();

    int par = 0;
    for (int tile = blockIdx.x; tile < NTILES; tile += gridDim.x, par ^= 1) {
        const uint32_t cur = sb + SBUF + par * BUFSZ;

        // ---- stage NEXT tile into the other buffer ----
        const int nxt = tile + gridDim.x;
        if (nxt < NTILES) {
            const float4* xr = (const float4*)(x + (long)(nxt * MT + w * 16) * DDIM);
            #pragma unroll 8
            for (int i = 0; i < 16; i++) {
                float4 f = xr[i * 32 + l];
                xsq_acc = fmaf(pc.x * f.x, f.x, xsq_acc);
                xsq_acc = fmaf(pc.y * f.y, f.y, xsq_acc);
                xsq_acc = fmaf(pc.z * f.z, f.z, xsq_acc);
                xsq_acc = fmaf(pc.w * f.w, f.w, xsq_acc);
                __nv_bfloat162 lo = __floats2bfloat162_rn(f.x, f.y);
                __nv_bfloat162 hi = __floats2bfloat162_rn(f.z, f.w);
                uint2 v;
                v.x = *(uint32_t*)&lo;
                v.y = *(uint32_t*)&hi;
                *(uint2*)(smem + SBUF + (par ^ 1) * BUFSZ + (w * 16 + i) * RSTRIDE + l * 8) = v;
            }
        }

        // ---- compute: warp w = all 128 rows x its 32 cols; no-max exp2 epilogue ----
        #pragma unroll 1
        for (int mt = 0; mt < 8; mt++) {
            float acc[4][4] = {};
            uint32_t a0[4], a1[4];
            const uint32_t rowad = cur + (mt * 16 + ((m & 1) << 3) + r) * RSTRIDE
                                 + (((m >> 1) << 3)) * 2;
            ldm_x4(rowad, a0[0], a0[1], a0[2], a0[3]);
            #pragma unroll
            for (int ks = 0; ks < 8; ks++) {
                uint32_t* ac = (ks & 1) ? a1 : a0;
                uint32_t* an = (ks & 1) ? a0 : a1;
                if (ks < 7)
                    ldm_x4(rowad + ((ks + 1) << 5), an[0], an[1], an[2], an[3]);
                #pragma unroll
                for (int t = 0; t < 4; t++)
                    mma16816(acc[t], ac, &B[ks][t >> 1][(t & 1) * 2]);
            }
            // per-lane 8-col partial sum of exp2(v), no max, no shfl
            #pragma unroll
            for (int sub = 0; sub < 2; sub++) {
                float s01 = ex2f(fmaf(acc[0][sub * 2],     L2E, av[0]))
                          + ex2f(fmaf(acc[0][sub * 2 + 1], L2E, av[1]));
                float s23 = ex2f(fmaf(acc[1][sub * 2],     L2E, av[2]))
                          + ex2f(fmaf(acc[1][sub * 2 + 1], L2E, av[3]));
                float s45 = ex2f(fmaf(acc[2][sub * 2],     L2E, av[4]))
                          + ex2f(fmaf(acc[2][sub * 2 + 1], L2E, av[5]));
                float s67 = ex2f(fmaf(acc[3][sub * 2],     L2E, av[6]))
                          + ex2f(fmaf(acc[3][sub * 2 + 1], L2E, av[7]));
                const float s = (s01 + s23) + (s45 + s67);
                const int row = mt * 16 + sub * 8 + (l >> 2);
                // slot = w*4 + (l&3); stride 36 floats -> all 32 lanes hit distinct banks
                ((float*)(smem + SPART))[row * 36 + w * 4 + (l & 3)] = s;
            }
        }
        __syncthreads();

        // ---- merge: pure deterministic fp32 sum of 32 partials + one lg2 per row ----
        if (tid < MT) {
            const float4* pr = (const float4*)(smem + SPART + tid * 144);
            float s = 0.f;
            #pragma unroll
            for (int j = 0; j < 8; j++) {
                float4 f = pr[j];
                s += ((f.x + f.y) + (f.z + f.w));
            }
            acc_thr += LN2 * (lg2f(s) - CSHIFT);
        }
        __syncthreads();
    }

    // fold thread-local xsq (additive pass-through of logsumexp)
    acc_thr -= 0.5f * xsq_acc;

    // ---- deterministic block reduction ----
    float a = acc_thr;
    #pragma unroll
    for (int o = 16; o; o >>= 1) a += __shfl_xor_sync(0xFFFFFFFFu, a, o);
    if (l == 0) red_s[w] = a;
    __syncthreads();
    if (tid == 0) {
        float t = 0.f;
        #pragma unroll
        for (int i = 0; i < 8; i++) t += red_s[i];
        g_partials[blockIdx.x] = t;
        __threadfence();
        unsigned int c = atomicAdd(&g_count, 1u);
        last_flag = (c == (unsigned)(gridDim.x - 1)) ? 1u : 0u;
    }
    __syncthreads();

    // ---- last CTA: deterministic final reduction (fixed lane->index map) ----
    if (last_flag && w == 0) {
        float s = 0.f;
        #pragma unroll
        for (int i = l; i < NCTAS; i += 32) s += __ldcg(&g_partials[i]);
        #pragma unroll
        for (int o = 16; o; o >>= 1) s += __shfl_xor_sync(0xFFFFFFFFu, s, o);
        if (l == 0) {
            out[0] = -s;
            g_count = 0;          // reset for next graph replay
            __threadfence();
        }
    }
}

extern "C" void kernel_launch(void* const* d_in, const int* in_sizes, int n_in,
                              void* d_out, int out_size) {
    const float* x    = (const float*)d_in[0];
    const float* mu   = (const float*)d_in[1];
    const float* prec = (const float*)d_in[2];
    float* out = (float*)d_out;

    cudaFuncSetAttribute(gmm_lse_kernel, cudaFuncAttributeMaxDynamicSharedMemorySize, SMEM_TOTAL);
    gmm_lse_kernel<<<NCTAS, THREADS, SMEM_TOTAL>>>(x, mu, prec, out);
}